// round 12
// baseline (speedup 1.0000x reference)
#include <cuda_runtime.h>
#include <cuda_fp16.h>

constexpr int N_NODES  = 131072;
constexpr int N_EDGES  = 2097152;
constexpr int N_GRAPHS = 2048;
constexpr int HID      = 64;
constexpr int IN_CH    = 12;
constexpr int OUT_CH   = 4;
constexpr int CSR_CAP  = N_EDGES + 4 * N_NODES;   // padded CSR capacity (pad 4)

// ---------------- scratch (device globals; statically zero-initialized) ----
// State discipline: every run leaves degi/gsum/gcnt re-zeroed (self-restoring),
// so graph replays are deterministic without an init kernel.
// g_hs has ONE EXTRA ROW (index N_NODES) that is never written: it stays all
// zeros and serves as the target of CSR padding entries (exact no-op adds).
__device__ __half g_hs[(N_NODES + 1) * HID];
__device__ float  g_v  [N_NODES * HID];   // layer-1 activations (fp32)
__device__ float  g_dinv[N_NODES];        // rsqrt(deg+1)
__device__ int    g_degi[N_NODES];        // in-degree (re-zeroed by k_scan1)
__device__ int    g_rdeg[N_NODES];        // real in-degree
__device__ int    g_rowptr[N_NODES];      // PADDED CSR row starts (mult. of 4)
__device__ int    g_fill[N_NODES];        // fill cursors
__device__ int    g_bsum[128];            // scan block sums
__device__ int    g_csr[CSR_CAP];         // CSR src indices, padded w/ N_NODES
__device__ float  g_gsum[N_GRAPHS * HID]; // pooled sums (re-zeroed by k_fc)
__device__ float  g_gcnt[N_GRAPHS];       // pooled counts (re-zeroed by k_fc)
__device__ int    g_is64;                 // index dtype flag

// ---------------- helpers --------------------------------------------------
__device__ __forceinline__ void red_add_v4(float* p, float4 v) {
    asm volatile("red.global.add.v4.f32 [%0], {%1,%2,%3,%4};"
                 :: "l"(p), "f"(v.x), "f"(v.y), "f"(v.z), "f"(v.w) : "memory");
}
__device__ __forceinline__ void red_add_f32(float* p, float v) {
    asm volatile("red.global.add.f32 [%0], %1;" :: "l"(p), "f"(v) : "memory");
}
__device__ __forceinline__ int load_idx(const void* p, long i, int is64) {
    return is64 ? (int)((const long long*)p)[i] : ((const int*)p)[i];
}
__device__ __forceinline__ __half2 shfl_xor_h2(__half2 v, int m) {
    unsigned u = *(unsigned*)&v;
    u = __shfl_xor_sync(0xFFFFFFFFu, u, m);
    return *(__half2*)&u;
}

// ---------------- kernels --------------------------------------------------

// Detect int32 vs int64 indices: int64 values < 2^32 have all-zero high words.
__global__ void k_detect(const void* __restrict__ ei) {
    const int* p = (const int*)ei;
    int lane = threadIdx.x & 31;
    int nz = 0;
    #pragma unroll
    for (int k = 0; k < 16; ++k) nz += (p[2 * (lane * 16 + k) + 1] != 0);
    unsigned any = __ballot_sync(0xFFFFFFFFu, nz != 0);
    if (lane == 0) g_is64 = (any == 0) ? 1 : 0;
}

// In-degree at dst.
__global__ void k_deg(const void* __restrict__ ei) {
    int e = blockIdx.x * blockDim.x + threadIdx.x;
    if (e >= N_EDGES) return;
    int d = load_idx(ei, (long)N_EDGES + e, g_is64);
    atomicAdd(&g_degi[d], 1);
}

// Scan stage 1 over PADDED degrees (ceil(deg/4)*4); also stores real degree,
// computes dinv, and re-zeroes degi for the next replay.
__global__ void k_scan1() {
    __shared__ int s[256];
    int t = threadIdx.x;
    int base = blockIdx.x * 1024 + t * 4;
    int v0 = g_degi[base + 0], v1 = g_degi[base + 1];
    int v2 = g_degi[base + 2], v3 = g_degi[base + 3];
    g_degi[base + 0] = 0; g_degi[base + 1] = 0;
    g_degi[base + 2] = 0; g_degi[base + 3] = 0;
    g_rdeg[base + 0] = v0; g_rdeg[base + 1] = v1;
    g_rdeg[base + 2] = v2; g_rdeg[base + 3] = v3;
    g_dinv[base + 0] = rsqrtf((float)v0 + 1.0f);
    g_dinv[base + 1] = rsqrtf((float)v1 + 1.0f);
    g_dinv[base + 2] = rsqrtf((float)v2 + 1.0f);
    g_dinv[base + 3] = rsqrtf((float)v3 + 1.0f);
    int p0 = (v0 + 3) & ~3, p1 = (v1 + 3) & ~3;
    int p2 = (v2 + 3) & ~3, p3 = (v3 + 3) & ~3;
    int tsum = p0 + p1 + p2 + p3;
    s[t] = tsum;
    __syncthreads();
    #pragma unroll
    for (int off = 1; off < 256; off <<= 1) {
        int x = (t >= off) ? s[t - off] : 0;
        __syncthreads();
        s[t] += x;
        __syncthreads();
    }
    int excl = s[t] - tsum;
    g_rowptr[base + 0] = excl;
    g_rowptr[base + 1] = excl + p0;
    g_rowptr[base + 2] = excl + p0 + p1;
    g_rowptr[base + 3] = excl + p0 + p1 + p2;
    if (t == 255) g_bsum[blockIdx.x] = s[255];
}

// Scan stage 2+3 fused: every block redundantly scans the 128 block sums,
// adds offsets, initializes fill cursors, and writes CSR padding slots
// (dummy src = N_NODES -> the permanent zero row).
__global__ void k_scan3() {
    __shared__ int s[128];
    int t = threadIdx.x;
    if (t < 128) s[t] = g_bsum[t];
    __syncthreads();
    #pragma unroll
    for (int off = 1; off < 128; off <<= 1) {
        int x = 0;
        if (t < 128 && t >= off) x = s[t - off];
        __syncthreads();
        if (t < 128) s[t] += x;
        __syncthreads();
    }
    int i = blockIdx.x * blockDim.x + t;
    int blk = i >> 10;
    int boff = (blk == 0) ? 0 : s[blk - 1];   // exclusive
    int r = g_rowptr[i] + boff;
    g_rowptr[i] = r;
    g_fill[i]   = r;
    int deg  = g_rdeg[i];
    int pdeg = (deg + 3) & ~3;
    for (int p = deg; p < pdeg; ++p) g_csr[r + p] = N_NODES;
}

// Combined: blocks [0,8192) fill CSR; blocks [8192,12288) compute xw1.
__global__ void k_fill_xw1(const void* __restrict__ ei,
                           const float* __restrict__ x,
                           const float* __restrict__ W1) {
    if (blockIdx.x < 8192) {
        int e = blockIdx.x * 256 + threadIdx.x;
        int is64 = g_is64;
        int s = load_idx(ei, e, is64);
        int d = load_idx(ei, (long)N_EDGES + e, is64);
        int pos = atomicAdd(&g_fill[d], 1);
        g_csr[pos] = s;
    } else {
        __shared__ float W1s[IN_CH * HID];
        __shared__ float xs[8][IN_CH];
        int t = threadIdx.x;
        for (int i = t; i < IN_CH * HID; i += 256) W1s[i] = W1[i];
        int lane = t & 31, nl = t >> 5;
        int base = (blockIdx.x - 8192) * 32;
        __syncthreads();
        for (int it = 0; it < 4; ++it) {
            int node = base + it * 8 + nl;
            if (lane < IN_CH) xs[nl][lane] = x[(long)node * IN_CH + lane];
            __syncthreads();
            float acc0 = 0.0f, acc1 = 0.0f;
            #pragma unroll
            for (int k = 0; k < IN_CH; ++k) {
                float xv = xs[nl][k];
                float2 w = *(const float2*)(W1s + k * HID + (lane << 1));
                acc0 = fmaf(xv, w.x, acc0);
                acc1 = fmaf(xv, w.y, acc1);
            }
            float di = g_dinv[node];
            ((__half2*)g_hs)[((long)node << 5) + lane] =
                __floats2half2_rn(acc0 * di, acc1 * di);
            __syncthreads();
        }
    }
}

// CSR gather: ONE WARP PER NODE. Per chunk of 4 edges: one broadcast int4
// CSR load (all 32 lanes, same address), each 8-lane group selects its edge
// via SELs (no shfl in the loop), loads its 16B row segment -> 4 rows in
// flight, fully unconditional body (padded CSR + permanent zero row).
// Uniform per-warp trip count => zero intra-warp imbalance. fp16 accumulate;
// cross-group shfl_xor butterfly (per node) then fp32 epilogue on lanes 0-7.
// FINAL=0: v = relu(dinv*(sum+self)+b) -> g_v (fp32)
// FINAL=1: h2 = relu(...)              -> pooled RED into gsum/gcnt
template<int FINAL>
__global__ void k_gather(const float* __restrict__ b,
                         const void* __restrict__ batch) {
    int node = (blockIdx.x * blockDim.x + threadIdx.x) >> 5;
    int lane = threadIdx.x & 31;
    int li   = lane & 7;                 // segment within the 128B row
    int grp  = lane >> 3;                // which of 4 concurrent edges
    int start = g_rowptr[node];          // multiple of 4
    int pdeg  = (g_rdeg[node] + 3) & ~3;
    const int4* rows = (const int4*)g_hs;            // 8 int4 per 128B row
    const int4* cp   = (const int4*)(g_csr + start); // 16B-aligned
    __half2 zero = __float2half2_rn(0.0f);
    __half2 acc0 = zero, acc1 = zero, acc2 = zero, acc3 = zero;
    for (int off = 0; off < pdeg; off += 4) {
        int4 c = cp[off >> 2];           // broadcast: 4 src indices
        int s = (grp == 0) ? c.x : (grp == 1) ? c.y : (grp == 2) ? c.z : c.w;
        int4 v = rows[((long)s << 3) + li];
        const __half2* hv = (const __half2*)&v;
        acc0 = __hadd2(acc0, hv[0]);
        acc1 = __hadd2(acc1, hv[1]);
        acc2 = __hadd2(acc2, hv[2]);
        acc3 = __hadd2(acc3, hv[3]);
    }
    // merge the 4 groups' partials (each lane ends with the full sum for li)
    acc0 = __hadd2(acc0, shfl_xor_h2(acc0, 8));
    acc0 = __hadd2(acc0, shfl_xor_h2(acc0, 16));
    acc1 = __hadd2(acc1, shfl_xor_h2(acc1, 8));
    acc1 = __hadd2(acc1, shfl_xor_h2(acc1, 16));
    acc2 = __hadd2(acc2, shfl_xor_h2(acc2, 8));
    acc2 = __hadd2(acc2, shfl_xor_h2(acc2, 16));
    acc3 = __hadd2(acc3, shfl_xor_h2(acc3, 8));
    acc3 = __hadd2(acc3, shfl_xor_h2(acc3, 16));
    if (lane < 8) {
        float di = g_dinv[node];
        int4 sv = rows[((long)node << 3) + li];
        const __half2* sh = (const __half2*)&sv;
        float4 bA = ((const float4*)b)[li * 2];
        float4 bB = ((const float4*)b)[li * 2 + 1];
        float2 a0 = __half22float2(acc0), s0 = __half22float2(sh[0]);
        float2 a1 = __half22float2(acc1), s1 = __half22float2(sh[1]);
        float2 a2 = __half22float2(acc2), s2 = __half22float2(sh[2]);
        float2 a3 = __half22float2(acc3), s3 = __half22float2(sh[3]);
        float4 o1, o2;
        o1.x = fmaxf(di * (a0.x + s0.x) + bA.x, 0.0f);
        o1.y = fmaxf(di * (a0.y + s0.y) + bA.y, 0.0f);
        o1.z = fmaxf(di * (a1.x + s1.x) + bA.z, 0.0f);
        o1.w = fmaxf(di * (a1.y + s1.y) + bA.w, 0.0f);
        o2.x = fmaxf(di * (a2.x + s2.x) + bB.x, 0.0f);
        o2.y = fmaxf(di * (a2.y + s2.y) + bB.y, 0.0f);
        o2.z = fmaxf(di * (a3.x + s3.x) + bB.z, 0.0f);
        o2.w = fmaxf(di * (a3.y + s3.y) + bB.w, 0.0f);
        if (FINAL) {
            int g = load_idx(batch, node, g_is64);
            float* gp = g_gsum + ((long)g << 6) + (li << 3);
            red_add_v4(gp, o1);
            red_add_v4(gp + 4, o2);
            if (li == 0) red_add_f32(&g_gcnt[g], 1.0f);
        } else {
            float4* vp = (float4*)(g_v + ((long)node << 6) + (li << 3));
            vp[0] = o1;
            vp[1] = o2;
        }
    }
}

// hs = half2((v @ W2) * dinv). 64 nodes/block to amortize the W2 smem fill.
__global__ void k_layer2m(const float* __restrict__ W2) {
    __shared__ float W2s[HID * HID];   // 16 KB
    __shared__ float vs[8][HID];
    int t = threadIdx.x;
    for (int i = t; i < HID * HID; i += 256) W2s[i] = W2[i];
    int lane = t & 31, nl = t >> 5;
    int base = blockIdx.x * 64;
    __syncthreads();
    for (int it = 0; it < 8; ++it) {
        int node = base + it * 8 + nl;
        float2 vv = *(const float2*)(g_v + ((long)node << 6) + (lane << 1));
        vs[nl][2 * lane]     = vv.x;
        vs[nl][2 * lane + 1] = vv.y;
        __syncthreads();
        float acc0 = 0.0f, acc1 = 0.0f;
        #pragma unroll
        for (int c = 0; c < HID; ++c) {
            float v = vs[nl][c];
            float2 w = *(const float2*)(W2s + c * HID + (lane << 1));
            acc0 = fmaf(v, w.x, acc0);
            acc1 = fmaf(v, w.y, acc1);
        }
        float di = g_dinv[node];
        ((__half2*)g_hs)[((long)node << 5) + lane] =
            __floats2half2_rn(acc0 * di, acc1 * di);
        __syncthreads();
    }
}

// FC + sigmoid; re-zeroes gsum/gcnt for the next replay.
__global__ void k_fc(const float* __restrict__ Wfc, const float* __restrict__ bfc,
                     float* __restrict__ out) {
    int g = blockIdx.x * blockDim.x + threadIdx.x;
    if (g >= N_GRAPHS) return;
    float cnt = g_gcnt[g];
    g_gcnt[g] = 0.0f;
    float inv = 1.0f / fmaxf(cnt, 1.0f);
    float acc0 = bfc[0], acc1 = bfc[1], acc2 = bfc[2], acc3 = bfc[3];
    #pragma unroll 8
    for (int c = 0; c < HID; ++c) {
        float m = g_gsum[g * HID + c] * inv;
        g_gsum[g * HID + c] = 0.0f;
        acc0 = fmaf(m, Wfc[c * OUT_CH + 0], acc0);
        acc1 = fmaf(m, Wfc[c * OUT_CH + 1], acc1);
        acc2 = fmaf(m, Wfc[c * OUT_CH + 2], acc2);
        acc3 = fmaf(m, Wfc[c * OUT_CH + 3], acc3);
    }
    out[g * OUT_CH + 0] = 1.0f / (1.0f + expf(-acc0));
    out[g * OUT_CH + 1] = 1.0f / (1.0f + expf(-acc1));
    out[g * OUT_CH + 2] = 1.0f / (1.0f + expf(-acc2));
    out[g * OUT_CH + 3] = 1.0f / (1.0f + expf(-acc3));
}

// ---------------- launch ----------------------------------------------------
extern "C" void kernel_launch(void* const* d_in, const int* in_sizes, int n_in,
                              void* d_out, int out_size) {
    const float* x    = (const float*)d_in[0];
    const void*  ei   = d_in[1];
    const void*  batch= d_in[2];
    const float* W1   = (const float*)d_in[3];
    const float* b1   = (const float*)d_in[4];
    const float* W2   = (const float*)d_in[5];
    const float* b2   = (const float*)d_in[6];
    const float* Wfc  = (const float*)d_in[7];
    const float* bfc  = (const float*)d_in[8];
    float*       out  = (float*)d_out;

    k_detect  <<<1, 32>>>(ei);                            // 0
    k_deg     <<<N_EDGES / 256, 256>>>(ei);               // 1
    k_scan1   <<<128, 256>>>();                           // 2
    k_scan3   <<<N_NODES / 256, 256>>>();                 // 3
    k_fill_xw1<<<8192 + N_NODES / 32, 256>>>(ei, x, W1);  // 4
    k_gather<0><<<N_NODES / 8, 256>>>(b1, batch);         // 5
    k_layer2m <<<N_NODES / 64, 256>>>(W2);                // 6
    k_gather<1><<<N_NODES / 8, 256>>>(b2, batch);         // 7
    k_fc      <<<N_GRAPHS / 256, 256>>>(Wfc, bfc, out);   // 8
}

// round 16
// speedup vs baseline: 1.1818x; 1.1818x over previous
#include <cuda_runtime.h>
#include <cuda_fp16.h>

constexpr int N_NODES  = 131072;
constexpr int N_EDGES  = 2097152;
constexpr int N_GRAPHS = 2048;
constexpr int HID      = 64;
constexpr int IN_CH    = 12;
constexpr int OUT_CH   = 4;

// ---------------- scratch (device globals; statically zero-initialized) ----
// State discipline: every run leaves degi/gsum/gcnt re-zeroed (self-restoring);
// rowptr/fill/dinv/rdeg are recomputed from scratch each run.
// Messages are FP8 e4m3: one node row = 64 B = 8 uint2. Forced 16B alignment.
__device__ __align__(16) uint2 g_hs[N_NODES * 8];
__device__ float  g_v  [N_NODES * HID];   // layer-1 activations (fp32)
__device__ float  g_dinv[N_NODES];        // rsqrt(deg+1)
__device__ int    g_degi[N_NODES];        // in-degree (re-zeroed by k_scan1)
__device__ int    g_rdeg[N_NODES];        // real in-degree
__device__ int    g_rowptr[N_NODES];      // CSR row starts (global, absolute)
__device__ int    g_fill[N_NODES];        // fill cursors (absolute, set by scan3)
__device__ int    g_bsum[128];            // scan block sums
__device__ int    g_csr[N_EDGES];         // CSR src indices (dst-sorted)
__device__ float  g_gsum[N_GRAPHS * HID]; // pooled sums (re-zeroed by k_fc)
__device__ float  g_gcnt[N_GRAPHS];       // pooled counts (re-zeroed by k_fc)
__device__ int    g_is64;                 // index dtype flag

// ---------------- helpers --------------------------------------------------
__device__ __forceinline__ void red_add_v4(float* p, float4 v) {
    asm volatile("red.global.add.v4.f32 [%0], {%1,%2,%3,%4};"
                 :: "l"(p), "f"(v.x), "f"(v.y), "f"(v.z), "f"(v.w) : "memory");
}
__device__ __forceinline__ void red_add_f32(float* p, float v) {
    asm volatile("red.global.add.f32 [%0], %1;" :: "l"(p), "f"(v) : "memory");
}
__device__ __forceinline__ int load_idx(const void* p, long i, int is64) {
    return is64 ? (int)((const long long*)p)[i] : ((const int*)p)[i];
}
// two packed e4m3 -> half2 (low byte -> .x, high byte -> .y)
__device__ __forceinline__ __half2 fp8x2_to_h2(unsigned short u) {
    unsigned r;
    asm("cvt.rn.f16x2.e4m3x2 %0, %1;" : "=r"(r) : "h"(u));
    return *(__half2*)&r;
}
// two floats -> packed e4m3x2 (hi -> high byte, lo -> low byte)
__device__ __forceinline__ unsigned short f2_to_fp8x2(float hi, float lo) {
    unsigned short r;
    asm("cvt.rn.satfinite.e4m3x2.f32 %0, %1, %2;" : "=h"(r) : "f"(hi), "f"(lo));
    return r;
}

// ---------------- kernels --------------------------------------------------

// Detect int32 vs int64 indices: int64 values < 2^32 have all-zero high words.
__global__ void k_detect(const void* __restrict__ ei) {
    const int* p = (const int*)ei;
    int lane = threadIdx.x & 31;
    int nz = 0;
    #pragma unroll
    for (int k = 0; k < 16; ++k) nz += (p[2 * (lane * 16 + k) + 1] != 0);
    unsigned any = __ballot_sync(0xFFFFFFFFu, nz != 0);
    if (lane == 0) g_is64 = (any == 0) ? 1 : 0;
}

// In-degree at dst.
__global__ void k_deg(const void* __restrict__ ei) {
    int e = blockIdx.x * blockDim.x + threadIdx.x;
    if (e >= N_EDGES) return;
    int d = load_idx(ei, (long)N_EDGES + e, g_is64);
    atomicAdd(&g_degi[d], 1);
}

// Scan stage 1: per-block (1024 elems) partial scans; also stores real degree,
// computes dinv, and re-zeroes degi for the next replay.
__global__ void k_scan1() {
    __shared__ int s[256];
    int t = threadIdx.x;
    int base = blockIdx.x * 1024 + t * 4;
    int v0 = g_degi[base + 0], v1 = g_degi[base + 1];
    int v2 = g_degi[base + 2], v3 = g_degi[base + 3];
    g_degi[base + 0] = 0; g_degi[base + 1] = 0;
    g_degi[base + 2] = 0; g_degi[base + 3] = 0;
    g_rdeg[base + 0] = v0; g_rdeg[base + 1] = v1;
    g_rdeg[base + 2] = v2; g_rdeg[base + 3] = v3;
    g_dinv[base + 0] = rsqrtf((float)v0 + 1.0f);
    g_dinv[base + 1] = rsqrtf((float)v1 + 1.0f);
    g_dinv[base + 2] = rsqrtf((float)v2 + 1.0f);
    g_dinv[base + 3] = rsqrtf((float)v3 + 1.0f);
    int tsum = v0 + v1 + v2 + v3;
    s[t] = tsum;
    __syncthreads();
    #pragma unroll
    for (int off = 1; off < 256; off <<= 1) {
        int x = (t >= off) ? s[t - off] : 0;
        __syncthreads();
        s[t] += x;
        __syncthreads();
    }
    int excl = s[t] - tsum;
    g_rowptr[base + 0] = excl;
    g_rowptr[base + 1] = excl + v0;
    g_rowptr[base + 2] = excl + v0 + v1;
    g_rowptr[base + 3] = excl + v0 + v1 + v2;
    if (t == 255) g_bsum[blockIdx.x] = s[255];
}

// Scan stage 2+3 fused: every block redundantly scans the 128 block sums in
// shared memory, then adds offsets, finalizes rowptr and fill cursors.
__global__ void k_scan3() {
    __shared__ int s[128];
    int t = threadIdx.x;
    if (t < 128) s[t] = g_bsum[t];
    __syncthreads();
    #pragma unroll
    for (int off = 1; off < 128; off <<= 1) {
        int x = 0;
        if (t < 128 && t >= off) x = s[t - off];
        __syncthreads();
        if (t < 128) s[t] += x;
        __syncthreads();
    }
    int i = blockIdx.x * blockDim.x + t;
    int blk = i >> 10;
    int boff = (blk == 0) ? 0 : s[blk - 1];   // exclusive
    int r = g_rowptr[i] + boff;
    g_rowptr[i] = r;
    g_fill[i]   = r;
}

// Combined: blocks [0,8192) fill CSR; blocks [8192,12288) compute xw1 (FP8).
__global__ void k_fill_xw1(const void* __restrict__ ei,
                           const float* __restrict__ x,
                           const float* __restrict__ W1) {
    if (blockIdx.x < 8192) {
        int e = blockIdx.x * 256 + threadIdx.x;
        int is64 = g_is64;
        int s = load_idx(ei, e, is64);
        int d = load_idx(ei, (long)N_EDGES + e, is64);
        int pos = atomicAdd(&g_fill[d], 1);
        g_csr[pos] = s;
    } else {
        __shared__ float W1s[IN_CH * HID];
        __shared__ float xs[8][IN_CH];
        int t = threadIdx.x;
        for (int i = t; i < IN_CH * HID; i += 256) W1s[i] = W1[i];
        int lane = t & 31, nl = t >> 5;
        int base = (blockIdx.x - 8192) * 32;
        __syncthreads();
        for (int it = 0; it < 4; ++it) {
            int node = base + it * 8 + nl;
            if (lane < IN_CH) xs[nl][lane] = x[(long)node * IN_CH + lane];
            __syncthreads();
            float acc0 = 0.0f, acc1 = 0.0f;
            #pragma unroll
            for (int k = 0; k < IN_CH; ++k) {
                float xv = xs[nl][k];
                float2 w = *(const float2*)(W1s + k * HID + (lane << 1));
                acc0 = fmaf(xv, w.x, acc0);
                acc1 = fmaf(xv, w.y, acc1);
            }
            float di = g_dinv[node];
            ((unsigned short*)g_hs)[node * 32 + lane] =
                f2_to_fp8x2(acc1 * di, acc0 * di);
            __syncthreads();
        }
    }
}

// CSR gather, round-7 proven structure: 4 nodes/warp, 8 lanes/node, shfl-
// broadcast indices, predicated loads. FP8 rows: 8B (uint2) per lane, convert
// to half2, accumulate in fp16; fp32 epilogue.
// FINAL=0: v = relu(dinv*(sum+self)+b) -> g_v (fp32)
// FINAL=1: h2 = relu(...)              -> pooled RED into gsum/gcnt
template<int FINAL>
__global__ void k_gather(const float* __restrict__ b,
                         const void* __restrict__ batch) {
    int warp = (blockIdx.x * blockDim.x + threadIdx.x) >> 5;
    int lane = threadIdx.x & 31;
    int li   = lane & 7;
    int node = warp * 4 + (lane >> 3);
    int start = g_rowptr[node];
    int deg   = g_rdeg[node];
    const uint2* rows = g_hs;                 // 8 uint2 per 64B row
    __half2 zero = __float2half2_rn(0.0f);
    __half2 acc0 = zero, acc1 = zero, acc2 = zero, acc3 = zero;
    for (int off = 0; __any_sync(0xFFFFFFFFu, off < deg); off += 8) {
        int rel = off + li;
        int sidx = (rel < deg) ? g_csr[start + rel] : -1;
        #pragma unroll
        for (int j = 0; j < 8; ++j) {
            int s = __shfl_sync(0xFFFFFFFFu, sidx, j, 8);
            if (s >= 0) {
                uint2 v = rows[((long)s << 3) + li];
                acc0 = __hadd2(acc0, fp8x2_to_h2((unsigned short)(v.x & 0xFFFF)));
                acc1 = __hadd2(acc1, fp8x2_to_h2((unsigned short)(v.x >> 16)));
                acc2 = __hadd2(acc2, fp8x2_to_h2((unsigned short)(v.y & 0xFFFF)));
                acc3 = __hadd2(acc3, fp8x2_to_h2((unsigned short)(v.y >> 16)));
            }
        }
    }
    float di = g_dinv[node];
    uint2 sv = rows[((long)node << 3) + li];
    float4 bA = ((const float4*)b)[li * 2];
    float4 bB = ((const float4*)b)[li * 2 + 1];
    float2 a0 = __half22float2(acc0);
    float2 a1 = __half22float2(acc1);
    float2 a2 = __half22float2(acc2);
    float2 a3 = __half22float2(acc3);
    float2 s0 = __half22float2(fp8x2_to_h2((unsigned short)(sv.x & 0xFFFF)));
    float2 s1 = __half22float2(fp8x2_to_h2((unsigned short)(sv.x >> 16)));
    float2 s2 = __half22float2(fp8x2_to_h2((unsigned short)(sv.y & 0xFFFF)));
    float2 s3 = __half22float2(fp8x2_to_h2((unsigned short)(sv.y >> 16)));
    float4 o1, o2;
    o1.x = fmaxf(di * (a0.x + s0.x) + bA.x, 0.0f);
    o1.y = fmaxf(di * (a0.y + s0.y) + bA.y, 0.0f);
    o1.z = fmaxf(di * (a1.x + s1.x) + bA.z, 0.0f);
    o1.w = fmaxf(di * (a1.y + s1.y) + bA.w, 0.0f);
    o2.x = fmaxf(di * (a2.x + s2.x) + bB.x, 0.0f);
    o2.y = fmaxf(di * (a2.y + s2.y) + bB.y, 0.0f);
    o2.z = fmaxf(di * (a3.x + s3.x) + bB.z, 0.0f);
    o2.w = fmaxf(di * (a3.y + s3.y) + bB.w, 0.0f);
    if (FINAL) {
        int g = load_idx(batch, node, g_is64);
        float* gp = g_gsum + ((long)g << 6) + (li << 3);
        red_add_v4(gp, o1);
        red_add_v4(gp + 4, o2);
        if (li == 0) red_add_f32(&g_gcnt[g], 1.0f);
    } else {
        float4* vp = (float4*)(g_v + ((long)node << 6) + (li << 3));
        vp[0] = o1;
        vp[1] = o2;
    }
}

// hs = fp8((v @ W2) * dinv). 64 nodes/block to amortize the W2 smem fill.
__global__ void k_layer2m(const float* __restrict__ W2) {
    __shared__ float W2s[HID * HID];   // 16 KB
    __shared__ float vs[8][HID];
    int t = threadIdx.x;
    for (int i = t; i < HID * HID; i += 256) W2s[i] = W2[i];
    int lane = t & 31, nl = t >> 5;
    int base = blockIdx.x * 64;
    __syncthreads();
    for (int it = 0; it < 8; ++it) {
        int node = base + it * 8 + nl;
        float2 vv = *(const float2*)(g_v + ((long)node << 6) + (lane << 1));
        vs[nl][2 * lane]     = vv.x;
        vs[nl][2 * lane + 1] = vv.y;
        __syncthreads();
        float acc0 = 0.0f, acc1 = 0.0f;
        #pragma unroll
        for (int c = 0; c < HID; ++c) {
            float v = vs[nl][c];
            float2 w = *(const float2*)(W2s + c * HID + (lane << 1));
            acc0 = fmaf(v, w.x, acc0);
            acc1 = fmaf(v, w.y, acc1);
        }
        float di = g_dinv[node];
        ((unsigned short*)g_hs)[node * 32 + lane] =
            f2_to_fp8x2(acc1 * di, acc0 * di);
        __syncthreads();
    }
}

// FC + sigmoid; re-zeroes gsum/gcnt for the next replay.
__global__ void k_fc(const float* __restrict__ Wfc, const float* __restrict__ bfc,
                     float* __restrict__ out) {
    int g = blockIdx.x * blockDim.x + threadIdx.x;
    if (g >= N_GRAPHS) return;
    float cnt = g_gcnt[g];
    g_gcnt[g] = 0.0f;
    float inv = 1.0f / fmaxf(cnt, 1.0f);
    float acc0 = bfc[0], acc1 = bfc[1], acc2 = bfc[2], acc3 = bfc[3];
    #pragma unroll 8
    for (int c = 0; c < HID; ++c) {
        float m = g_gsum[g * HID + c] * inv;
        g_gsum[g * HID + c] = 0.0f;
        acc0 = fmaf(m, Wfc[c * OUT_CH + 0], acc0);
        acc1 = fmaf(m, Wfc[c * OUT_CH + 1], acc1);
        acc2 = fmaf(m, Wfc[c * OUT_CH + 2], acc2);
        acc3 = fmaf(m, Wfc[c * OUT_CH + 3], acc3);
    }
    out[g * OUT_CH + 0] = 1.0f / (1.0f + expf(-acc0));
    out[g * OUT_CH + 1] = 1.0f / (1.0f + expf(-acc1));
    out[g * OUT_CH + 2] = 1.0f / (1.0f + expf(-acc2));
    out[g * OUT_CH + 3] = 1.0f / (1.0f + expf(-acc3));
}

// ---------------- launch ----------------------------------------------------
extern "C" void kernel_launch(void* const* d_in, const int* in_sizes, int n_in,
                              void* d_out, int out_size) {
    const float* x    = (const float*)d_in[0];
    const void*  ei   = d_in[1];
    const void*  batch= d_in[2];
    const float* W1   = (const float*)d_in[3];
    const float* b1   = (const float*)d_in[4];
    const float* W2   = (const float*)d_in[5];
    const float* b2   = (const float*)d_in[6];
    const float* Wfc  = (const float*)d_in[7];
    const float* bfc  = (const float*)d_in[8];
    float*       out  = (float*)d_out;

    k_detect  <<<1, 32>>>(ei);                            // 0
    k_deg     <<<N_EDGES / 256, 256>>>(ei);               // 1
    k_scan1   <<<128, 256>>>();                           // 2
    k_scan3   <<<N_NODES / 256, 256>>>();                 // 3
    k_fill_xw1<<<8192 + N_NODES / 32, 256>>>(ei, x, W1);  // 4
    k_gather<0><<<N_NODES / 32, 256>>>(b1, batch);        // 5
    k_layer2m <<<N_NODES / 64, 256>>>(W2);                // 6
    k_gather<1><<<N_NODES / 32, 256>>>(b2, batch);        // 7
    k_fc      <<<N_GRAPHS / 256, 256>>>(Wfc, bfc, out);   // 8
}